// round 10
// baseline (speedup 1.0000x reference)
#include <cuda_runtime.h>
#include <math.h>

#define K_BINS   8
#define TAIL     3.0f
#define MIN_W    0.001f
#define MIN_H    0.001f
#define MIN_D    0.001f

#define NROWS    8192
#define NDIMS    2048
#define NPAR     (K_BINS * 3 - 1)   // 23

#define TILE_D   64
#define THREADS  128
#define ROWS_PB  64                  // rows per block (2 row-slots x 32 rows)

__global__ __launch_bounds__(THREADS, 12)
void rqs_kernel(const float* __restrict__ inputs,
                const float* __restrict__ params,
                float* __restrict__ out_base)
{
    // sm_f4[bin][col] = {invw, c, ih, ich}
    // sm_f2[bin][col] = {dlo, s}
    // conflict-free for divergent bin: row strides (1024B, 512B) are multiples of 128B
    __shared__ float4 sm_f4[K_BINS][TILE_D];   // 8 KB (also reused as params staging)
    __shared__ float2 sm_f2[K_BINS][TILE_D];   // 4 KB
    __shared__ float  sm_kn[7][TILE_D];        // 1.75 KB

    const int tid  = threadIdx.x;
    const int col0 = blockIdx.x * TILE_D;

    // ---- stage params coalesced into scratch (reuse sm_f4 memory) ----
    {
        float* scratch = (float*)sm_f4;                 // 2048 floats >= 1472
        const float* gsrc = params + (size_t)col0 * NPAR;
        #pragma unroll
        for (int i = 0; i < (TILE_D * NPAR + THREADS - 1) / THREADS; i++) {
            const int k = tid + i * THREADS;
            if (k < TILE_D * NPAR) scratch[k] = gsrc[k];
        }
    }
    __syncthreads();

    // ---- each build thread pulls its 23 params into registers ----
    float uw[K_BINS], uh[K_BINS], ud[K_BINS - 1];
    if (tid < TILE_D) {
        const float* sp = (const float*)sm_f4 + tid * NPAR;  // stride 23: conflict-free
        #pragma unroll
        for (int j = 0; j < K_BINS; j++)      uw[j] = sp[j];
        #pragma unroll
        for (int j = 0; j < K_BINS; j++)      uh[j] = sp[K_BINS + j];
        #pragma unroll
        for (int j = 0; j < K_BINS - 1; j++)  ud[j] = sp[2 * K_BINS + j];
    }
    __syncthreads();   // all reads of scratch done before tables overwrite it

    // ---------------- table build: one thread per dim ----------------
    if (tid < TILE_D) {
        float cw[K_BINS + 1], ch[K_BINS + 1];
        {
            float m = uw[0];
            #pragma unroll
            for (int j = 1; j < K_BINS; j++) m = fmaxf(m, uw[j]);
            float e[K_BINS], ssum = 0.0f;
            #pragma unroll
            for (int j = 0; j < K_BINS; j++) { e[j] = expf(uw[j] - m); ssum += e[j]; }
            float inv_s = 1.0f / ssum;
            float acc = 0.0f;
            cw[0] = -TAIL;
            #pragma unroll
            for (int j = 0; j < K_BINS; j++) {
                float wj = fmaf(1.0f - MIN_W * K_BINS, e[j] * inv_s, MIN_W);
                acc += wj;
                cw[j + 1] = fmaf(2.0f * TAIL, acc, -TAIL);
            }
            cw[K_BINS] = TAIL;
        }
        {
            float m = uh[0];
            #pragma unroll
            for (int j = 1; j < K_BINS; j++) m = fmaxf(m, uh[j]);
            float e[K_BINS], ssum = 0.0f;
            #pragma unroll
            for (int j = 0; j < K_BINS; j++) { e[j] = expf(uh[j] - m); ssum += e[j]; }
            float inv_s = 1.0f / ssum;
            float acc = 0.0f;
            ch[0] = -TAIL;
            #pragma unroll
            for (int j = 0; j < K_BINS; j++) {
                float hj = fmaf(1.0f - MIN_H * K_BINS, e[j] * inv_s, MIN_H);
                acc += hj;
                ch[j + 1] = fmaf(2.0f * TAIL, acc, -TAIL);
            }
            ch[K_BINS] = TAIL;
        }
        float dv[K_BINS + 1];
        dv[0] = 1.0f;                  // MIN_D + softplus(log(exp(1-MIN_D)-1)) == 1
        dv[K_BINS] = 1.0f;
        #pragma unroll
        for (int j = 0; j < K_BINS - 1; j++)
            dv[j + 1] = MIN_D + log1pf(expf(ud[j]));

        #pragma unroll
        for (int j = 0; j < 7; j++) sm_kn[j][tid] = cw[j + 1];

        #pragma unroll
        for (int b = 0; b < K_BINS; b++) {
            const float iw    = cw[b + 1] - cw[b];
            const float ih    = ch[b + 1] - ch[b];
            const float invw  = 1.0f / iw;
            const float delta = ih * invw;
            const float dlo   = dv[b];
            const float s     = dlo + dv[b + 1] - 2.0f * delta;
            sm_f4[b][tid] = make_float4(invw, -cw[b] * invw, ih, ch[b]);
            sm_f2[b][tid] = make_float2(dlo, s);
        }
    }
    __syncthreads();

    // ---------------- main elementwise loop ----------------
    const int tx  = tid & (TILE_D - 1);
    const int ty  = tid >> 6;                    // 0 or 1
    const int col = col0 + tx;
    const int row0 = blockIdx.y * ROWS_PB + ty;

    // knots -> registers (fixed for this thread's column)
    const float k0 = sm_kn[0][tx], k1 = sm_kn[1][tx], k2 = sm_kn[2][tx];
    const float k3 = sm_kn[3][tx], k4 = sm_kn[4][tx], k5 = sm_kn[5][tx];
    const float k6 = sm_kn[6][tx];

    const float4* __restrict__ fA = &sm_f4[0][tx];   // + idx*TILE_D float4
    const float2* __restrict__ fB = &sm_f2[0][tx];   // + idx*TILE_D float2

    const size_t base = (size_t)row0 * NDIMS + col;
    const float* __restrict__ pin = inputs + base;
    float* __restrict__ po = out_base + base;
    float* __restrict__ pl = out_base + (size_t)NROWS * NDIMS + base;

    #pragma unroll 1
    for (int ii = 0; ii < 8; ii++) {
        float gv[4];
        #pragma unroll
        for (int j = 0; j < 4; j++) gv[j] = pin[j * 2 * NDIMS];

        #pragma unroll
        for (int j = 0; j < 4; j++) {
            const float g = gv[j];

            // register select-tree binary search
            const bool p3 = g >= k3;
            const float m1 = p3 ? k5 : k1;
            const bool p2 = g >= m1;
            const float hi = p2 ? k6 : k4;
            const float lo = p2 ? k2 : k0;
            const float m2 = p3 ? hi : lo;
            const bool p1 = g >= m2;
            const int idx = (p3 ? 4 : 0) + (p2 ? 2 : 0) + (p1 ? 1 : 0);

            const float4 A = fA[idx * TILE_D];   // {invw, c, ih, ich}
            const float2 B = fB[idx * TILE_D];   // {dlo, s}

            const float delta = A.z * A.x;           // ih * invw
            const float th  = fmaf(g, A.x, A.y);     // theta
            const float th2 = th * th;
            const float t1m = th - th2;              // theta*(1-theta)

            const float den  = fmaf(B.y, t1m, delta);
            const float rden = __fdividef(1.0f, den);

            const float nm = fmaf(delta, th2, B.x * t1m);
            const float o  = fmaf(A.z * nm, rden, A.w);

            const float dmd = delta - B.x;
            const float dn  = fmaf(fmaf(B.y, th, dmd + dmd), th, B.x);
            const float dd  = delta * rden;
            const float l   = __logf(dn * (dd * dd));

            const bool inside = fabsf(g) <= TAIL;
            const int ro = j * 2 * NDIMS;
            po[ro] = inside ? o : g;
            pl[ro] = inside ? l : 0.0f;
        }
        pin += 8 * NDIMS;
        po  += 8 * NDIMS;
        pl  += 8 * NDIMS;
    }
}

extern "C" void kernel_launch(void* const* d_in, const int* in_sizes, int n_in,
                              void* d_out, int out_size)
{
    const float* inputs = (const float*)d_in[0];
    const float* params = (const float*)d_in[1];
    float* out = (float*)d_out;

    dim3 grid(NDIMS / TILE_D, NROWS / ROWS_PB);   // (32, 128)
    rqs_kernel<<<grid, THREADS>>>(inputs, params, out);
}

// round 11
// speedup vs baseline: 1.1157x; 1.1157x over previous
#include <cuda_runtime.h>
#include <math.h>

#define K_BINS   8
#define TAIL     3.0f
#define MIN_W    0.001f
#define MIN_H    0.001f
#define MIN_D    0.001f

#define NROWS    8192
#define NDIMS    2048
#define NPAR     (K_BINS * 3 - 1)   // 23

#define TILE_D   64                  // columns per block
#define THREADS  128                 // 32 col-pairs x 4 row slots
#define ROWS_PB  64                  // rows per block (4 slots x 16 rows)

// one spline-element evaluation; c (column parity) must be a compile-time constant
__device__ __forceinline__ void rqs_one(
    const float g,
    const float k0, const float k1, const float k2, const float k3,
    const float k4, const float k5, const float k6,
    const float4* __restrict__ fA, const float2* __restrict__ fB,
    const int coff,                    // c*32, compile-time
    float& r_o, float& r_l)
{
    const bool p3 = g >= k3;
    const float m1 = p3 ? k5 : k1;
    const bool p2 = g >= m1;
    const float hi = p2 ? k6 : k4;
    const float lo = p2 ? k2 : k0;
    const float m2 = p3 ? hi : lo;
    const bool p1 = g >= m2;
    const int idx = (p3 ? 4 : 0) + (p2 ? 2 : 0) + (p1 ? 1 : 0);

    const float4 A = fA[idx * 64 + coff];   // {invw, c, ih, ich}
    const float2 B = fB[idx * 64 + coff];   // {dlo, s}

    const float delta = A.z * A.x;           // ih * invw
    const float th  = fmaf(g, A.x, A.y);     // theta
    const float th2 = th * th;
    const float t1m = th - th2;              // theta*(1-theta)

    const float den  = fmaf(B.y, t1m, delta);
    const float rden = __fdividef(1.0f, den);

    const float nm = fmaf(delta, th2, B.x * t1m);
    const float o  = fmaf(A.z * nm, rden, A.w);

    const float dmd = delta - B.x;
    const float dn  = fmaf(fmaf(B.y, th, dmd + dmd), th, B.x);
    const float dd  = delta * rden;
    const float l   = __logf(dn * (dd * dd));

    const bool inside = fabsf(g) <= TAIL;
    r_o = inside ? o : g;
    r_l = inside ? l : 0.0f;
}

__global__ __launch_bounds__(THREADS, 9)
void rqs_kernel(const float* __restrict__ inputs,
                const float* __restrict__ params,
                float* __restrict__ out_base)
{
    // tables interleaved by column parity:
    //   sm_f4[bin][par][t] = {invw, c, ih, ich}   for col = 2t+par
    //   sm_f2[bin][par][t] = {dlo, s}
    // element lane addr: f4 idx*1024 + par*512 + 16t (conflict-free),
    //                    f2 idx*512  + par*256 + 8t  (conflict-free)
    __shared__ float4 sm_f4[K_BINS][2][TILE_D / 2];   // 8 KB (reused as staging)
    __shared__ float2 sm_f2[K_BINS][2][TILE_D / 2];   // 4 KB
    __shared__ float  sm_kn[7][TILE_D];               // 1.75 KB

    const int tid  = threadIdx.x;
    const int col0 = blockIdx.x * TILE_D;

    // ---- stage params coalesced into scratch (reuse sm_f4 memory) ----
    {
        float* scratch = (float*)sm_f4;                 // 2048 floats >= 1472
        const float* gsrc = params + (size_t)col0 * NPAR;
        #pragma unroll
        for (int i = 0; i < (TILE_D * NPAR + THREADS - 1) / THREADS; i++) {
            const int k = tid + i * THREADS;
            if (k < TILE_D * NPAR) scratch[k] = gsrc[k];
        }
    }
    __syncthreads();

    // ---- each build thread pulls its 23 params into registers ----
    float uw[K_BINS], uh[K_BINS], ud[K_BINS - 1];
    if (tid < TILE_D) {
        const float* sp = (const float*)sm_f4 + tid * NPAR;  // stride 23: conflict-free
        #pragma unroll
        for (int j = 0; j < K_BINS; j++)      uw[j] = sp[j];
        #pragma unroll
        for (int j = 0; j < K_BINS; j++)      uh[j] = sp[K_BINS + j];
        #pragma unroll
        for (int j = 0; j < K_BINS - 1; j++)  ud[j] = sp[2 * K_BINS + j];
    }
    __syncthreads();   // all reads of scratch done before tables overwrite it

    // ---------------- table build: one thread per dim ----------------
    if (tid < TILE_D) {
        float cw[K_BINS + 1], ch[K_BINS + 1];
        {
            float m = uw[0];
            #pragma unroll
            for (int j = 1; j < K_BINS; j++) m = fmaxf(m, uw[j]);
            float e[K_BINS], ssum = 0.0f;
            #pragma unroll
            for (int j = 0; j < K_BINS; j++) { e[j] = expf(uw[j] - m); ssum += e[j]; }
            float inv_s = 1.0f / ssum;
            float acc = 0.0f;
            cw[0] = -TAIL;
            #pragma unroll
            for (int j = 0; j < K_BINS; j++) {
                float wj = fmaf(1.0f - MIN_W * K_BINS, e[j] * inv_s, MIN_W);
                acc += wj;
                cw[j + 1] = fmaf(2.0f * TAIL, acc, -TAIL);
            }
            cw[K_BINS] = TAIL;
        }
        {
            float m = uh[0];
            #pragma unroll
            for (int j = 1; j < K_BINS; j++) m = fmaxf(m, uh[j]);
            float e[K_BINS], ssum = 0.0f;
            #pragma unroll
            for (int j = 0; j < K_BINS; j++) { e[j] = expf(uh[j] - m); ssum += e[j]; }
            float inv_s = 1.0f / ssum;
            float acc = 0.0f;
            ch[0] = -TAIL;
            #pragma unroll
            for (int j = 0; j < K_BINS; j++) {
                float hj = fmaf(1.0f - MIN_H * K_BINS, e[j] * inv_s, MIN_H);
                acc += hj;
                ch[j + 1] = fmaf(2.0f * TAIL, acc, -TAIL);
            }
            ch[K_BINS] = TAIL;
        }
        float dv[K_BINS + 1];
        dv[0] = 1.0f;                  // MIN_D + softplus(log(exp(1-MIN_D)-1)) == 1
        dv[K_BINS] = 1.0f;
        #pragma unroll
        for (int j = 0; j < K_BINS - 1; j++)
            dv[j + 1] = MIN_D + log1pf(expf(ud[j]));

        #pragma unroll
        for (int j = 0; j < 7; j++) sm_kn[j][tid] = cw[j + 1];

        const int par = tid & 1;
        const int t   = tid >> 1;
        #pragma unroll
        for (int b = 0; b < K_BINS; b++) {
            const float iw    = cw[b + 1] - cw[b];
            const float ih    = ch[b + 1] - ch[b];
            const float invw  = 1.0f / iw;
            const float delta = ih * invw;
            const float dlo   = dv[b];
            const float s     = dlo + dv[b + 1] - 2.0f * delta;
            sm_f4[b][par][t] = make_float4(invw, -cw[b] * invw, ih, ch[b]);
            sm_f2[b][par][t] = make_float2(dlo, s);
        }
    }
    __syncthreads();

    // ---------------- main loop: 2 adjacent columns per thread ----------------
    const int tx  = tid & 31;                    // col-pair index
    const int ty  = tid >> 5;                    // row slot 0..3
    const int col = col0 + 2 * tx;
    const int row0 = blockIdx.y * ROWS_PB + ty;

    // knots for both columns -> named registers
    const float ka0 = sm_kn[0][2*tx],   ka1 = sm_kn[1][2*tx],   ka2 = sm_kn[2][2*tx];
    const float ka3 = sm_kn[3][2*tx],   ka4 = sm_kn[4][2*tx],   ka5 = sm_kn[5][2*tx];
    const float ka6 = sm_kn[6][2*tx];
    const float kb0 = sm_kn[0][2*tx+1], kb1 = sm_kn[1][2*tx+1], kb2 = sm_kn[2][2*tx+1];
    const float kb3 = sm_kn[3][2*tx+1], kb4 = sm_kn[4][2*tx+1], kb5 = sm_kn[5][2*tx+1];
    const float kb6 = sm_kn[6][2*tx+1];

    const float4* __restrict__ fA = &sm_f4[0][0][tx];   // bin stride 64 f4, par stride 32 f4
    const float2* __restrict__ fB = &sm_f2[0][0][tx];   // bin stride 64 f2, par stride 32 f2

    const size_t base = (size_t)row0 * NDIMS + col;
    const float2* __restrict__ pin = (const float2*)(inputs + base);
    float2* __restrict__ po = (float2*)(out_base + base);
    float2* __restrict__ pl = (float2*)(out_base + (size_t)NROWS * NDIMS + base);
    const int RSTRIDE = 4 * NDIMS / 2;           // float2 units per 4-row step

    #pragma unroll 1
    for (int ii = 0; ii < 4; ii++) {
        float2 gv[4];
        #pragma unroll
        for (int j = 0; j < 4; j++) gv[j] = pin[j * RSTRIDE];

        #pragma unroll
        for (int j = 0; j < 4; j++) {
            float2 ro, rl;
            rqs_one(gv[j].x, ka0, ka1, ka2, ka3, ka4, ka5, ka6, fA, fB, 0,  ro.x, rl.x);
            rqs_one(gv[j].y, kb0, kb1, kb2, kb3, kb4, kb5, kb6, fA, fB, 32, ro.y, rl.y);
            po[j * RSTRIDE] = ro;
            pl[j * RSTRIDE] = rl;
        }
        pin += 4 * RSTRIDE;
        po  += 4 * RSTRIDE;
        pl  += 4 * RSTRIDE;
    }
}

extern "C" void kernel_launch(void* const* d_in, const int* in_sizes, int n_in,
                              void* d_out, int out_size)
{
    const float* inputs = (const float*)d_in[0];
    const float* params = (const float*)d_in[1];
    float* out = (float*)d_out;

    dim3 grid(NDIMS / TILE_D, NROWS / ROWS_PB);   // (32, 128)
    rqs_kernel<<<grid, THREADS>>>(inputs, params, out);
}